// round 1
// baseline (speedup 1.0000x reference)
#include <cuda_runtime.h>

#define NROWS 4096
#define DIM   512
#define KH    8
#define RSUB  64
#define CDIM  512      /* KH*RSUB */
#define MAXNB 512

// ---------------- scratch (device globals; no allocations allowed) ----------
__device__ float g_W [DIM * CDIM];             // W[d][c]  = U[c/64][d][c%64]
__device__ float g_Wt[CDIM * DIM];             // Wt[c][d] = W[d][c]
__device__ float g_Z   [(size_t)NROWS * CDIM]; // Z[i][c]
__device__ float g_Zagg[(size_t)NROWS * CDIM]; // Z_agg[i][c]

// ---------------- packed f32x2 helpers (full-rate FMA on sm_103a) -----------
__device__ __forceinline__ unsigned long long fma2(unsigned long long a,
                                                   unsigned long long b,
                                                   unsigned long long c) {
    unsigned long long d;
    asm("fma.rn.f32x2 %0, %1, %2, %3;" : "=l"(d) : "l"(a), "l"(b), "l"(c));
    return d;
}
__device__ __forceinline__ unsigned long long pack2(float x, float y) {
    unsigned long long d;
    asm("mov.b64 %0, {%1, %2};" : "=l"(d) : "f"(x), "f"(y));
    return d;
}
__device__ __forceinline__ float2 unpack2(unsigned long long v) {
    float2 r;
    asm("mov.b64 {%0, %1}, %2;" : "=f"(r.x), "=f"(r.y) : "l"(v));
    return r;
}

// ---------------- repack U into W and Wt; init orth scalar ------------------
__global__ void repack_kernel(const float* __restrict__ U, float* __restrict__ scal) {
    int idx = blockIdx.x * 256 + threadIdx.x;
    if (idx >= DIM * CDIM) return;
    int d = idx >> 9;
    int c = idx & 511;
    float v = U[((c >> 6) << 15) + (d << 6) + (c & 63)];
    g_W [(d << 9) + c] = v;
    g_Wt[(c << 9) + d] = v;
    if (idx == 0 && scal) *scal = 0.f;
}

// ---------------- tiled SGEMM with f32x2 accumulation -----------------------
// MODE 0: g_Z = A(H, 4096x512) * g_W (512x512)
// MODE 1: out = relu(H + 0.5*(g_Zagg * g_Wt) - thr)
template <int MODE>
__global__ void __launch_bounds__(256)
sgemm_kernel(const float* __restrict__ Aext, float* __restrict__ Cext,
             const float* __restrict__ Hin, const float* __restrict__ thr) {
    constexpr int BM = 128, BN = 64, BK = 16;
    __shared__ __align__(16) float As[BK][BM + 4];
    __shared__ __align__(16) float Bs[BK][BN + 4];

    const float* A = (MODE == 0) ? Aext   : g_Zagg;
    const float* B = (MODE == 0) ? g_W    : g_Wt;
    float*       C = (MODE == 0) ? g_Z    : Cext;

    const int tid = threadIdx.x;
    const int bm  = blockIdx.y * BM;
    const int bn  = blockIdx.x * BN;
    const int tr  = tid >> 4;   // 0..15 -> rows tr*8..tr*8+7
    const int tc  = tid & 15;   // 0..15 -> cols tc*4..tc*4+3

    unsigned long long acc[8][2];
#pragma unroll
    for (int i = 0; i < 8; i++) { acc[i][0] = 0ull; acc[i][1] = 0ull; }

    const int K = DIM, Nn = CDIM;
    for (int k0 = 0; k0 < K; k0 += BK) {
        // A tile: 128x16, transposed into As[kk][m], float4 global loads
#pragma unroll
        for (int it = 0; it < 2; it++) {
            int lin = it * 256 + tid;      // float4 units
            int m   = lin >> 2;
            int k4  = lin & 3;
            float4 v = *(const float4*)&A[(size_t)(bm + m) * K + k0 + k4 * 4];
            As[k4 * 4 + 0][m] = v.x;
            As[k4 * 4 + 1][m] = v.y;
            As[k4 * 4 + 2][m] = v.z;
            As[k4 * 4 + 3][m] = v.w;
        }
        // B tile: 16x64
        {
            int n4 = tid & 15;
            int kk = tid >> 4;
            float4 v = *(const float4*)&B[(size_t)(k0 + kk) * Nn + bn + n4 * 4];
            *(float4*)&Bs[kk][n4 * 4] = v;
        }
        __syncthreads();
#pragma unroll
        for (int kk = 0; kk < BK; kk++) {
            float4 a0 = *(const float4*)&As[kk][tr * 8];
            float4 a1 = *(const float4*)&As[kk][tr * 8 + 4];
            ulonglong2 bv = *(const ulonglong2*)&Bs[kk][tc * 4];
            float av[8] = {a0.x, a0.y, a0.z, a0.w, a1.x, a1.y, a1.z, a1.w};
#pragma unroll
            for (int ii = 0; ii < 8; ii++) {
                unsigned long long a2 = pack2(av[ii], av[ii]);
                acc[ii][0] = fma2(a2, bv.x, acc[ii][0]);
                acc[ii][1] = fma2(a2, bv.y, acc[ii][1]);
            }
        }
        __syncthreads();
    }

#pragma unroll
    for (int ii = 0; ii < 8; ii++) {
        int row = bm + tr * 8 + ii;
        int col = bn + tc * 4;
        float2 v0 = unpack2(acc[ii][0]);
        float2 v1 = unpack2(acc[ii][1]);
        if (MODE == 0) {
            *(float4*)&C[(size_t)row * Nn + col] = make_float4(v0.x, v0.y, v1.x, v1.y);
        } else {
            float4 h = *(const float4*)&Hin[(size_t)row * DIM + col];
            float4 t = *(const float4*)&thr[col];
            float4 o;
            o.x = fmaxf(h.x + 0.5f * v0.x - t.x, 0.f);
            o.y = fmaxf(h.y + 0.5f * v0.y - t.y, 0.f);
            o.z = fmaxf(h.z + 0.5f * v1.x - t.z, 0.f);
            o.w = fmaxf(h.w + 0.5f * v1.y - t.w, 0.f);
            *(float4*)&C[(size_t)row * DIM + col] = o;
        }
    }
}

// ---------------- sparse masked attention: one CTA per row ------------------
__global__ void __launch_bounds__(256)
attn_kernel(const float* __restrict__ adj) {
    const int i   = blockIdx.x;
    const int tid = threadIdx.x;

    __shared__ float zi[CDIM];
    __shared__ int   nbr[MAXNB];
    __shared__ float sc[KH * MAXNB];   // 16 KB
    __shared__ int   cnts[256];
    __shared__ int   s_cnt;

    zi[tid]       = g_Z[(size_t)i * CDIM + tid];
    zi[tid + 256] = g_Z[(size_t)i * CDIM + 256 + tid];

    // --- deterministic neighbor compaction (16 contiguous j per thread) ---
    const float* arow = adj + (size_t)i * NROWS;
    int base = tid * 16;
    unsigned flags = 0;
    int cnt = 0;
#pragma unroll
    for (int q = 0; q < 4; q++) {
        float4 v = *(const float4*)&arow[base + q * 4];
        if (v.x != 0.f) { flags |= 1u << (q * 4 + 0); cnt++; }
        if (v.y != 0.f) { flags |= 1u << (q * 4 + 1); cnt++; }
        if (v.z != 0.f) { flags |= 1u << (q * 4 + 2); cnt++; }
        if (v.w != 0.f) { flags |= 1u << (q * 4 + 3); cnt++; }
    }
    cnts[tid] = cnt;
    __syncthreads();
    // inclusive Hillis-Steele scan over 256 counts
    for (int off = 1; off < 256; off <<= 1) {
        int add = (tid >= off) ? cnts[tid - off] : 0;
        __syncthreads();
        cnts[tid] += add;
        __syncthreads();
    }
    int incl = cnts[tid];
    if (tid == 255) s_cnt = incl;
    int pos = incl - cnt;
#pragma unroll
    for (int q = 0; q < 16; q++) {
        if ((flags >> q) & 1) {
            if (pos < MAXNB) nbr[pos] = base + q;
            pos++;
        }
    }
    __syncthreads();
    int n = s_cnt;
    if (n > MAXNB) n = MAXNB;   // statistically unreachable guard

    // --- scores: one half-warp per (head, neighbor) task ---
    const int hw = tid >> 4;    // half-warp id 0..15
    const int hl = tid & 15;
    for (int t = hw; t < KH * n; t += 16) {
        int k  = t & 7;
        int jj = t >> 3;
        int j  = nbr[jj];
        float4 q = *(const float4*)(zi + k * 64 + hl * 4);
        float4 z = *(const float4*)(g_Z + (size_t)j * CDIM + k * 64 + hl * 4);
        float d = q.x * z.x + q.y * z.y + q.z * z.z + q.w * z.w;
        d += __shfl_xor_sync(0xffffffffu, d, 8);
        d += __shfl_xor_sync(0xffffffffu, d, 4);
        d += __shfl_xor_sync(0xffffffffu, d, 2);
        d += __shfl_xor_sync(0xffffffffu, d, 1);
        if (hl == 0) sc[k * MAXNB + jj] = d * 0.125f;   // 1/sqrt(64)
    }
    __syncthreads();

    // --- softmax: warp w handles head w (masked entries == exact 0 in ref) ---
    {
        const int wid = tid >> 5, lane = tid & 31;
        float m = -1e30f;
        for (int jj = lane; jj < n; jj += 32) m = fmaxf(m, sc[wid * MAXNB + jj]);
#pragma unroll
        for (int o = 16; o; o >>= 1) m = fmaxf(m, __shfl_xor_sync(0xffffffffu, m, o));
        float s = 0.f;
        for (int jj = lane; jj < n; jj += 32) {
            float e = __expf(sc[wid * MAXNB + jj] - m);
            sc[wid * MAXNB + jj] = e;
            s += e;
        }
#pragma unroll
        for (int o = 16; o; o >>= 1) s += __shfl_xor_sync(0xffffffffu, s, o);
        float inv = 1.f / s;
        for (int jj = lane; jj < n; jj += 32) sc[wid * MAXNB + jj] *= inv;
    }
    __syncthreads();

    // --- aggregate: column-parallel, Z rows are L2-resident (8 MB) ---
#pragma unroll
    for (int half = 0; half < 2; half++) {
        int c = tid + half * 256;
        int k = c >> 6;
        const float* scr = sc + k * MAXNB;
        float acc = 0.f;
        for (int jj = 0; jj < n; jj++)
            acc += scr[jj] * g_Z[(size_t)nbr[jj] * CDIM + c];
        g_Zagg[(size_t)i * CDIM + c] = acc;
    }
}

// ---------------- orthogonality loss: one CTA per head pair (k<l) -----------
__global__ void __launch_bounds__(256)
orth_kernel(const float* __restrict__ U, float* __restrict__ out) {
    int b = blockIdx.x;   // 0..27
    int k = 0, l = 1;
    {
        int c = b;
#pragma unroll
        for (int kk = 0; kk < 8; kk++) {
            int row = 7 - kk;
            if (c < row) { k = kk; l = kk + 1 + c; break; }
            c -= row;
        }
    }
    __shared__ float su[32][64];
    __shared__ float sv[32][64];
    const int tid = threadIdx.x;
    const int tr = tid >> 4, tc = tid & 15;
    float g[4][4] = {};
    const float* Uk = U + (size_t)k * DIM * RSUB;
    const float* Ul = U + (size_t)l * DIM * RSUB;
    for (int d0 = 0; d0 < DIM; d0 += 32) {
#pragma unroll
        for (int it = 0; it < 8; it++) {
            int lin = it * 256 + tid;
            int dd = lin >> 6, r = lin & 63;
            su[dd][r] = Uk[(size_t)(d0 + dd) * 64 + r];
            sv[dd][r] = Ul[(size_t)(d0 + dd) * 64 + r];
        }
        __syncthreads();
#pragma unroll 8
        for (int dd = 0; dd < 32; dd++) {
            float a[4], bb[4];
#pragma unroll
            for (int u = 0; u < 4; u++) { a[u] = su[dd][tr * 4 + u]; bb[u] = sv[dd][tc * 4 + u]; }
#pragma unroll
            for (int u = 0; u < 4; u++)
#pragma unroll
                for (int v = 0; v < 4; v++) g[u][v] += a[u] * bb[v];
        }
        __syncthreads();
    }
    float s = 0.f;
#pragma unroll
    for (int u = 0; u < 4; u++)
#pragma unroll
        for (int v = 0; v < 4; v++) s += g[u][v] * g[u][v];
#pragma unroll
    for (int o = 16; o; o >>= 1) s += __shfl_xor_sync(0xffffffffu, s, o);
    __shared__ float wsum[8];
    if ((tid & 31) == 0) wsum[tid >> 5] = s;
    __syncthreads();
    if (tid < 8) {
        float t = wsum[tid];
#pragma unroll
        for (int o = 4; o; o >>= 1) t += __shfl_xor_sync(0xffu, t, o);
        if (tid == 0) atomicAdd(out, t);
    }
}

// ---------------- launch ----------------------------------------------------
extern "C" void kernel_launch(void* const* d_in, const int* in_sizes, int n_in,
                              void* d_out, int out_size) {
    const float* H   = (const float*)d_in[0];   // [4096, 512]
    const float* adj = (const float*)d_in[1];   // [4096, 4096]
    const float* U   = (const float*)d_in[2];   // [8, 512, 64]
    const float* thr = (const float*)d_in[3];   // [512]
    float* out = (float*)d_out;                 // [4096*512] H_out (+ orth scalar)

    float* orth_ptr = (out_size > NROWS * DIM) ? (out + (size_t)NROWS * DIM) : nullptr;

    repack_kernel<<<(DIM * CDIM + 255) / 256, 256>>>(U, orth_ptr);
    sgemm_kernel<0><<<dim3(CDIM / 64, NROWS / 128), 256>>>(H, nullptr, nullptr, nullptr);
    attn_kernel<<<NROWS, 256>>>(adj);
    sgemm_kernel<1><<<dim3(DIM / 64, NROWS / 128), 256>>>(nullptr, out, H, thr);
    if (orth_ptr) orth_kernel<<<28, 256>>>(U, orth_ptr);
}